// round 14
// baseline (speedup 1.0000x reference)
#include <cuda_runtime.h>
#include <cuda_fp16.h>
#include <cstdint>

#define B_  2
#define S_  4096
#define D_  512
#define H_  8
#define DK_ 64
#define M_  (B_*S_)   // 8192

// Byte-offset scratch map (f16 regions):
//  GQ 0MB (natural), GK 8MB (ilv), GVT 16MB (ilv along s), GOH 24MB (ilv),
//  QF 32MB, KF 40MB, VF 48MB (cvt inputs, ilv), WF 56MB (4x 512KB weights, ilv)
#define MB_ (1024*1024)
#define OFF_GQ   0
#define OFF_GK   (8*MB_)
#define OFF_GVT  (16*MB_)
#define OFF_GOH  (24*MB_)
#define OFF_QF   (32*MB_)
#define OFF_WF   (56*MB_)
__device__ __align__(16) unsigned char g_scr[58 * MB_];

#define ONES_H2 0x3C003C00u

// ---------------- helpers ----------------
__device__ __forceinline__ uint32_t packh2(float lo, float hi){
    uint32_t u; asm("cvt.rn.f16x2.f32 %0, %1, %2;" : "=r"(u) : "f"(hi), "f"(lo));
    return u;
}
__device__ __forceinline__ uint32_t ex2h2(uint32_t x){
    uint32_t r; asm("ex2.approx.f16x2 %0, %1;" : "=r"(r) : "r"(x)); return r;
}
__device__ __forceinline__ void mma16(float* c, uint32_t a0, uint32_t a1, uint32_t a2,
                                      uint32_t a3, uint32_t b0, uint32_t b1){
    asm volatile("mma.sync.aligned.m16n8k16.row.col.f32.f16.f16.f32 "
        "{%0,%1,%2,%3}, {%4,%5,%6,%7}, {%8,%9}, {%0,%1,%2,%3};"
        : "+f"(c[0]), "+f"(c[1]), "+f"(c[2]), "+f"(c[3])
        : "r"(a0), "r"(a1), "r"(a2), "r"(a3), "r"(b0), "r"(b1));
}
__device__ __forceinline__ void mma16h(uint32_t& c0, uint32_t& c1,
                                       uint32_t a0, uint32_t a1, uint32_t a2,
                                       uint32_t a3, uint32_t b0, uint32_t b1){
    asm volatile("mma.sync.aligned.m16n8k16.row.col.f16.f16.f16.f16 "
        "{%0,%1}, {%2,%3,%4,%5}, {%6,%7}, {%0,%1};"
        : "+r"(c0), "+r"(c1)
        : "r"(a0), "r"(a1), "r"(a2), "r"(a3), "r"(b0), "r"(b1));
}

// cp.async 16B, commit, wait-all
#define CP16(dst_u32, src_ptr) \
    asm volatile("cp.async.cg.shared.global [%0], [%1], 16;" \
        :: "r"(dst_u32), "l"(src_ptr) : "memory")
#define CP_COMMIT() asm volatile("cp.async.commit_group;" ::: "memory")
#define CP_WAIT0()  asm volatile("cp.async.wait_group 0;" ::: "memory")

// Pair-interleaved group format (GLOBAL + SMEM): a 16-half k-group is stored
// as uint pairs in order {p01,p89,p23,p1011,p45,p1213,p67,p1415}; pair j ->
// uint slot ILVu(j) = j<4 ? 2j : 2(j-4)+1. Matches the fragment pairing the
// LDS.64 loads expect. Loaders are now pure 16B copies (cp.async).
__device__ __forceinline__ int ilvu(int j){ return (j < 4) ? 2 * j : 2 * (j - 4) + 1; }

// SMEM tile addressing, padded non-wrapping swizzle (affine in row,kb):
#define KB_STRIDE  2176
#define HALF_TILE  8704                     // 4 * KB_STRIDE
__device__ __forceinline__ uint32_t grp_off(int row, int kb){
    return ((row >> 6) * HALF_TILE) + kb * KB_STRIDE + (((row & 63) + kb) << 5);
}
__device__ __forceinline__ uint32_t grp_off64(int j, int kb){
    return kb * KB_STRIDE + ((j + kb) << 5);
}

// ---------------- f32 -> f16 conversion pre-pass (emits interleaved) ----------------
__global__ __launch_bounds__(256) void cvt_f16(
    const float* __restrict__ q, const float* __restrict__ k,
    const float* __restrict__ v,
    const float* __restrict__ Wq, const float* __restrict__ Wk,
    const float* __restrict__ Wv, const float* __restrict__ Wo)
{
    const int z = blockIdx.z;
    const float* src; __half* dst; int n;
    if (z < 3) {
        src = (z == 0) ? q : (z == 1) ? k : v;
        dst = (__half*)(g_scr + OFF_QF + (size_t)z * 8 * MB_);
        n = M_ * D_;
    } else {
        src = (z == 3) ? Wq : (z == 4) ? Wk : (z == 5) ? Wv : Wo;
        dst = (__half*)(g_scr + OFF_WF + (size_t)(z - 3) * 512 * 1024);
        n = D_ * D_;
    }
    int i = (blockIdx.x * 256 + threadIdx.x) * 16;
    if (i >= n) return;
    float4 c0 = *(const float4*)&src[i];
    float4 c1 = *(const float4*)&src[i + 4];
    float4 c2 = *(const float4*)&src[i + 8];
    float4 c3 = *(const float4*)&src[i + 12];
    // interleaved: {p01,p89,p23,p1011 | p45,p1213,p67,p1415}
    *(uint4*)&dst[i]     = make_uint4(packh2(c0.x,c0.y), packh2(c2.x,c2.y),
                                      packh2(c0.z,c0.w), packh2(c2.z,c2.w));
    *(uint4*)&dst[i + 8] = make_uint4(packh2(c1.x,c1.y), packh2(c3.x,c3.y),
                                      packh2(c1.z,c1.w), packh2(c3.z,c3.w));
}

// ---------------- projection GEMMs (cp.async loaders, f16 mma, BM=128 BN=128) ----------------
#define PJ_A_BYTES (2 * HALF_TILE)               // 17408
#define PJ_W_BYTES (2 * HALF_TILE)               // 17408
#define PJ_BUF_BYTES (PJ_A_BYTES + PJ_W_BYTES)   // 34816
#define PJ_SMEM (2 * PJ_BUF_BYTES)               // 69632

// QKV projection: blockIdx.z selects {q->GQ(natural), k->GK(ilv), v->GVT(ilv,transposed)}
__global__ __launch_bounds__(256, 2) void proj_qkv(float qscale)
{
    extern __shared__ char smc[];
    const int z = blockIdx.z;
    const __half* A = (const __half*)(g_scr + OFF_QF + (size_t)z * 8 * MB_);
    const __half* W = (const __half*)(g_scr + OFF_WF + (size_t)z * 512 * 1024);
    __half* out = (__half*)(g_scr + (size_t)z * 8 * MB_);
    const float scale = (z == 0) ? qscale : 1.0f;

    const int tid = threadIdx.x, lane = tid & 31, w = tid >> 5;
    const int wr = w >> 1, wc = w & 1;               // 4 x 2 warp grid
    const int qq = lane >> 2, t = lane & 3;
    const int m0 = blockIdx.y * 128, n0 = blockIdx.x * 128;
    const uint32_t smem_u = (uint32_t)__cvta_generic_to_shared(smc);

    auto load_chunk = [&](int ch){
        const int k0 = ch * 64, bsel = ch & 1;
        const uint32_t abuf = smem_u + bsel * PJ_BUF_BYTES;
        const uint32_t wbuf = abuf + PJ_A_BYTES;
        #pragma unroll
        for (int i = 0; i < 2; i++) {
            int u = tid + i * 256;
            int kb = u & 3, row = u >> 2;             // [0,128)
            const __half* sa = &A[(size_t)(m0 + row) * 512 + k0 + kb * 16];
            const __half* sw = &W[(size_t)(n0 + row) * 512 + k0 + kb * 16];
            uint32_t da = abuf + grp_off(row, kb);
            uint32_t dw = wbuf + grp_off(row, kb);
            CP16(da, sa); CP16(da + 16, sa + 8);
            CP16(dw, sw); CP16(dw + 16, sw + 8);
        }
    };

    float c[2][8][4] = {};
    load_chunk(0); CP_COMMIT();

    for (int ch = 0; ch < 8; ch++) {
        CP_WAIT0();
        __syncthreads();
        if (ch < 7) { load_chunk(ch + 1); CP_COMMIT(); }
        const char* abuf = smc + (ch & 1) * PJ_BUF_BYTES;
        const char* wbuf = abuf + PJ_A_BYTES;

        #pragma unroll
        for (int kb = 0; kb < 4; kb++) {
            uint2 af[2][2];
            #pragma unroll
            for (int blk = 0; blk < 2; blk++) {
                int r = wr * 32 + blk * 16 + qq;
                af[blk][0] = *(const uint2*)(abuf + grp_off(r,     kb) + t * 8);
                af[blk][1] = *(const uint2*)(abuf + grp_off(r + 8, kb) + t * 8);
            }
            #pragma unroll
            for (int ni = 0; ni < 8; ni++) {
                uint2 b = *(const uint2*)(wbuf + grp_off(wc * 64 + ni * 8 + qq, kb) + t * 8);
                mma16(c[0][ni], af[0][0].x, af[0][1].x, af[0][0].y, af[0][1].y, b.x, b.y);
                mma16(c[1][ni], af[1][0].x, af[1][1].x, af[1][0].y, af[1][1].y, b.x, b.y);
            }
        }
        __syncthreads();
    }

    const int h = (n0 >> 6) + wc;                    // 64-col warp block = one head
    #pragma unroll
    for (int blk = 0; blk < 2; blk++)
        #pragma unroll
        for (int ni = 0; ni < 8; ni++) {
            // natural column (z==0) vs interleaved column (z==1)
            const int dkc_nat = ni * 8 + 2 * t;
            const int dkc_ilv = (ni >> 1) * 16 + 4 * t + 2 * (ni & 1);
            #pragma unroll
            for (int h2 = 0; h2 < 2; h2++) {
                int m = m0 + wr * 32 + blk * 16 + qq + h2 * 8;
                int b = m >> 12, s = m & 4095;
                float v0 = c[blk][ni][h2 * 2 + 0] * scale;
                float v1 = c[blk][ni][h2 * 2 + 1] * scale;
                if (z < 2) {
                    int dkc = (z == 0) ? dkc_nat : dkc_ilv;
                    *(__half2*)(out + ((size_t)(b * H_ + h) * S_ + s) * DK_ + dkc)
                        = __floats2half2_rn(v0, v1);
                } else {
                    // gVT: interleave along s within 16-groups
                    int sl = s & 15;
                    int s_ilv = (s & ~15) + 2 * ilvu(sl >> 1) + (sl & 1);
                    out[((size_t)(b * H_ + h) * DK_ + dkc_nat    ) * S_ + s_ilv] = __float2half(v0);
                    out[((size_t)(b * H_ + h) * DK_ + dkc_nat + 1) * S_ + s_ilv] = __float2half(v1);
                }
            }
        }
}

// Output projection: GOH (ilv) gathered @ Wo^T (ilv) -> f32 out
__global__ __launch_bounds__(256, 2) void proj_out(float* __restrict__ Cout)
{
    extern __shared__ char smc[];
    const __half* Agat = (const __half*)(g_scr + OFF_GOH);
    const __half* W    = (const __half*)(g_scr + OFF_WF + 3 * 512 * 1024);

    const int tid = threadIdx.x, lane = tid & 31, w = tid >> 5;
    const int wr = w >> 1, wc = w & 1;
    const int qq = lane >> 2, t = lane & 3;
    const int m0 = blockIdx.y * 128, n0 = blockIdx.x * 128;
    const uint32_t smem_u = (uint32_t)__cvta_generic_to_shared(smc);

    auto load_chunk = [&](int ch){
        const int k0 = ch * 64, bsel = ch & 1;
        const uint32_t abuf = smem_u + bsel * PJ_BUF_BYTES;
        const uint32_t wbuf = abuf + PJ_A_BYTES;
        #pragma unroll
        for (int i = 0; i < 2; i++) {
            int u = tid + i * 256;
            int kb = u & 3, row = u >> 2;
            int m = m0 + row, b = m >> 12, s = m & 4095;
            const __half* sa = &Agat[((size_t)(b * H_ + ch) * S_ + s) * DK_ + kb * 16];
            const __half* sw = &W[(size_t)(n0 + row) * 512 + k0 + kb * 16];
            uint32_t da = abuf + grp_off(row, kb);
            uint32_t dw = wbuf + grp_off(row, kb);
            CP16(da, sa); CP16(da + 16, sa + 8);
            CP16(dw, sw); CP16(dw + 16, sw + 8);
        }
    };

    float c[2][8][4] = {};
    load_chunk(0); CP_COMMIT();

    for (int ch = 0; ch < 8; ch++) {
        CP_WAIT0();
        __syncthreads();
        if (ch < 7) { load_chunk(ch + 1); CP_COMMIT(); }
        const char* abuf = smc + (ch & 1) * PJ_BUF_BYTES;
        const char* wbuf = abuf + PJ_A_BYTES;

        #pragma unroll
        for (int kb = 0; kb < 4; kb++) {
            uint2 af[2][2];
            #pragma unroll
            for (int blk = 0; blk < 2; blk++) {
                int r = wr * 32 + blk * 16 + qq;
                af[blk][0] = *(const uint2*)(abuf + grp_off(r,     kb) + t * 8);
                af[blk][1] = *(const uint2*)(abuf + grp_off(r + 8, kb) + t * 8);
            }
            #pragma unroll
            for (int ni = 0; ni < 8; ni++) {
                uint2 b = *(const uint2*)(wbuf + grp_off(wc * 64 + ni * 8 + qq, kb) + t * 8);
                mma16(c[0][ni], af[0][0].x, af[0][1].x, af[0][0].y, af[0][1].y, b.x, b.y);
                mma16(c[1][ni], af[1][0].x, af[1][1].x, af[1][0].y, af[1][1].y, b.x, b.y);
            }
        }
        __syncthreads();
    }

    #pragma unroll
    for (int blk = 0; blk < 2; blk++)
        #pragma unroll
        for (int ni = 0; ni < 8; ni++)
            #pragma unroll
            for (int h2 = 0; h2 < 2; h2++) {
                int m = m0 + wr * 32 + blk * 16 + qq + h2 * 8;
                int n = n0 + wc * 64 + ni * 8 + 2 * t;
                *(float2*)&Cout[(size_t)m * 512 + n] =
                    make_float2(c[blk][ni][h2 * 2 + 0], c[blk][ni][h2 * 2 + 1]);
            }
}

// ---------------- attention (cp.async loader; f16 S-accum + mask bias) ----------------
#define KF_BYTES  (4 * KB_STRIDE)           // 8704
#define VF_BYTES  (4 * KB_STRIDE)           // 8704
#define BUF_BYTES (KF_BYTES + VF_BYTES)     // 17408
#define SM_BUF0   1024
#define ATT_SMEM  (SM_BUF0 + 2 * BUF_BYTES) // 35840

__global__ __launch_bounds__(128, 3) void attn_kernel(const int* __restrict__ mask)
{
    extern __shared__ char smc[];
    __half* maskh = (__half*)smc;           // [2][64] additive bias: 0 or -30000

    const int tid = threadIdx.x, lane = tid & 31, w = tid >> 5;
    const int q = lane >> 2, t = lane & 3;
    const int bh = blockIdx.y, bb = bh >> 3;
    const int q0 = blockIdx.x * 128;
    const uint32_t smem_u = (uint32_t)__cvta_generic_to_shared(smc);

    const __half* gQh  = (const __half*)(g_scr + OFF_GQ);
    const __half* gKh  = (const __half*)(g_scr + OFF_GK);
    const __half* gVTh = (const __half*)(g_scr + OFF_GVT);
    __half*       gOh  = (__half*)(g_scr + OFF_GOH);
    const size_t base    = (size_t)bh * S_ * DK_;
    const size_t vt_base = (size_t)bh * DK_ * S_;

    // ---- Q fragments from gQ (natural layout), loop-invariant ----
    const int r0 = w * 32 + q;
    uint32_t qa[2][4][4];
    #pragma unroll
    for (int blk = 0; blk < 2; blk++) {
        const __half* qp = gQh + base + (size_t)(q0 + r0 + blk * 16) * DK_;
        #pragma unroll
        for (int kb = 0; kb < 4; kb++) {
            qa[blk][kb][0] = *(const uint32_t*)(qp + kb * 16 + 2 * t);
            qa[blk][kb][1] = *(const uint32_t*)(qp + 8 * DK_ + kb * 16 + 2 * t);
            qa[blk][kb][2] = *(const uint32_t*)(qp + kb * 16 + 2 * t + 8);
            qa[blk][kb][3] = *(const uint32_t*)(qp + 8 * DK_ + kb * 16 + 2 * t + 8);
        }
    }

    auto load_tile = [&](int it) {
        const int n0 = it * 64, bsel = it & 1;
        const uint32_t kbuf = smem_u + SM_BUF0 + bsel * BUF_BYTES;
        const uint32_t vbuf = kbuf + KF_BYTES;
        #pragma unroll
        for (int i = 0; i < 2; i++) {
            int u = tid + i * 128;
            int kb = u & 3, j = u >> 2;               // j in [0,64)
            const __half* sk = gKh + base + (size_t)(n0 + j) * DK_ + kb * 16;
            const __half* sv = gVTh + vt_base + (size_t)j * S_ + n0 + kb * 16;
            uint32_t dk = kbuf + grp_off64(j, kb);
            uint32_t dv = vbuf + grp_off64(j, kb);
            CP16(dk, sk); CP16(dk + 16, sk + 8);
            CP16(dv, sv); CP16(dv + 16, sv + 8);
        }
        if (tid < 64)
            maskh[bsel * 64 + tid] =
                __float2half(mask[bb * S_ + n0 + tid] ? 0.f : -30000.f);
    };

    float o[2][8][4] = {};
    float ol[2][4] = {};                    // ones-column accumulators (l)

    load_tile(0); CP_COMMIT();

    for (int it = 0; it < 64; it++) {
        CP_WAIT0();
        __syncthreads();
        if (it < 63) { load_tile(it + 1); CP_COMMIT(); }

        const int bsel = it & 1;
        const char* kbuf = smc + SM_BUF0 + bsel * BUF_BYTES;
        const char* vbuf = kbuf + KF_BYTES;
        const __half* mb = maskh + bsel * 64;

        // ---- S = mask_bias + Q @ K^T  (f16 accumulators) ----
        uint32_t s[2][8][2];
        #pragma unroll
        for (int ni = 0; ni < 8; ni++) {
            uint32_t m2 = *(const uint32_t*)(mb + ni * 8 + 2 * t);
            s[0][ni][0] = m2; s[0][ni][1] = m2;
            s[1][ni][0] = m2; s[1][ni][1] = m2;
        }
        #pragma unroll
        for (int kb = 0; kb < 4; kb++) {
            const char* kp = kbuf + kb * KB_STRIDE + (q + kb) * 32 + t * 8;
            #pragma unroll
            for (int ni = 0; ni < 8; ni++) {
                uint2 b = *(const uint2*)(kp + ni * 256);
                mma16h(s[0][ni][0], s[0][ni][1],
                       qa[0][kb][0], qa[0][kb][1], qa[0][kb][2], qa[0][kb][3], b.x, b.y);
                mma16h(s[1][ni][0], s[1][ni][1],
                       qa[1][kb][0], qa[1][kb][1], qa[1][kb][2], qa[1][kb][3], b.x, b.y);
            }
        }

        // ---- softmax: p = ex2(s) in place; s IS the PV A-fragment set ----
        #pragma unroll
        for (int ni = 0; ni < 8; ni++) {
            s[0][ni][0] = ex2h2(s[0][ni][0]); s[0][ni][1] = ex2h2(s[0][ni][1]);
            s[1][ni][0] = ex2h2(s[1][ni][0]); s[1][ni][1] = ex2h2(s[1][ni][1]);
        }

        // ---- O += P @ V, plus ones-column for l ----
        #pragma unroll
        for (int jb = 0; jb < 4; jb++) {
            const char* vp = vbuf + jb * KB_STRIDE + (q + jb) * 32 + t * 8;
            #pragma unroll
            for (int ni = 0; ni < 8; ni++) {
                uint2 b = *(const uint2*)(vp + ni * 256);
                mma16(o[0][ni], s[0][2*jb][0], s[0][2*jb][1],
                                s[0][2*jb+1][0], s[0][2*jb+1][1], b.x, b.y);
                mma16(o[1][ni], s[1][2*jb][0], s[1][2*jb][1],
                                s[1][2*jb+1][0], s[1][2*jb+1][1], b.x, b.y);
            }
            mma16(ol[0], s[0][2*jb][0], s[0][2*jb][1],
                         s[0][2*jb+1][0], s[0][2*jb+1][1], ONES_H2, ONES_H2);
            mma16(ol[1], s[1][2*jb][0], s[1][2*jb][1],
                         s[1][2*jb+1][0], s[1][2*jb+1][1], ONES_H2, ONES_H2);
        }
    }

    // ---- finalize: normalize + write GOH in interleaved format ----
    #pragma unroll
    for (int blk = 0; blk < 2; blk++) {
        const float l0 = ol[blk][0], l1 = ol[blk][2];
        const float inv0 = (l0 > 0.f) ? (1.f / l0) : 0.f;
        const float inv1 = (l1 > 0.f) ? (1.f / l1) : 0.f;
        const int rr = q0 + r0 + blk * 16;
        #pragma unroll
        for (int ni = 0; ni < 8; ni++) {
            int col = (ni >> 1) * 16 + 4 * t + 2 * (ni & 1);   // interleaved
            *(__half2*)(gOh + base + (size_t)(rr    ) * DK_ + col) =
                __floats2half2_rn(o[blk][ni][0] * inv0, o[blk][ni][1] * inv0);
            *(__half2*)(gOh + base + (size_t)(rr + 8) * DK_ + col) =
                __floats2half2_rn(o[blk][ni][2] * inv1, o[blk][ni][3] * inv1);
        }
    }
}

// ---------------- launch ----------------
extern "C" void kernel_launch(void* const* d_in, const int* in_sizes, int n_in,
                              void* d_out, int out_size)
{
    const float* q    = (const float*)d_in[0];
    const float* k    = (const float*)d_in[1];
    const float* v    = (const float*)d_in[2];
    const int*   mask = (const int*)  d_in[3];
    const float* Wq   = (const float*)d_in[4];
    const float* Wk   = (const float*)d_in[5];
    const float* Wv   = (const float*)d_in[6];
    const float* Wo   = (const float*)d_in[7];
    float* out = (float*)d_out;

    cudaFuncSetAttribute(attn_kernel,
                         cudaFuncAttributeMaxDynamicSharedMemorySize, ATT_SMEM);
    cudaFuncSetAttribute(proj_qkv,
                         cudaFuncAttributeMaxDynamicSharedMemorySize, PJ_SMEM);
    cudaFuncSetAttribute(proj_out,
                         cudaFuncAttributeMaxDynamicSharedMemorySize, PJ_SMEM);

    // fold 1/sqrt(DK) * log2(e) into Q so attention works in exp2 domain
    const float qscale = 0.125f * 1.4426950408889634f;

    cvt_f16<<<dim3((M_ * D_) / (256 * 16), 1, 7), 256>>>(q, k, v, Wq, Wk, Wv, Wo);
    proj_qkv<<<dim3(D_ / 128, M_ / 128, 3), 256, PJ_SMEM>>>(qscale);
    attn_kernel<<<dim3(S_ / 128, B_ * H_), 128, ATT_SMEM>>>(mask);
    proj_out<<<dim3(D_ / 128, M_ / 128), 256, PJ_SMEM>>>(out);
}

// round 15
// speedup vs baseline: 1.3891x; 1.3891x over previous
#include <cuda_runtime.h>
#include <cuda_fp16.h>
#include <cstdint>

#define B_  2
#define S_  4096
#define D_  512
#define H_  8
#define DK_ 64
#define M_  (B_*S_)   // 8192

// Byte-offset scratch map (f16 regions):
//  GQ 0MB (natural), GK 8MB (ilv), GVT 16MB (ilv along s), GOH 24MB (ilv),
//  QF 32MB, KF 40MB, VF 48MB (cvt inputs, ilv), WF 56MB (4x 512KB weights, ilv)
#define MB_ (1024*1024)
#define OFF_GQ   0
#define OFF_GK   (8*MB_)
#define OFF_GVT  (16*MB_)
#define OFF_GOH  (24*MB_)
#define OFF_QF   (32*MB_)
#define OFF_WF   (56*MB_)
__device__ __align__(16) unsigned char g_scr[58 * MB_];

#define ONES_H2 0x3C003C00u

// ---------------- helpers ----------------
__device__ __forceinline__ uint32_t packh2(float lo, float hi){
    uint32_t u; asm("cvt.rn.f16x2.f32 %0, %1, %2;" : "=r"(u) : "f"(hi), "f"(lo));
    return u;
}
__device__ __forceinline__ uint32_t ex2h2(uint32_t x){
    uint32_t r; asm("ex2.approx.f16x2 %0, %1;" : "=r"(r) : "r"(x)); return r;
}
__device__ __forceinline__ void mma16(float* c, uint32_t a0, uint32_t a1, uint32_t a2,
                                      uint32_t a3, uint32_t b0, uint32_t b1){
    asm volatile("mma.sync.aligned.m16n8k16.row.col.f32.f16.f16.f32 "
        "{%0,%1,%2,%3}, {%4,%5,%6,%7}, {%8,%9}, {%0,%1,%2,%3};"
        : "+f"(c[0]), "+f"(c[1]), "+f"(c[2]), "+f"(c[3])
        : "r"(a0), "r"(a1), "r"(a2), "r"(a3), "r"(b0), "r"(b1));
}
__device__ __forceinline__ void mma16h(uint32_t& c0, uint32_t& c1,
                                       uint32_t a0, uint32_t a1, uint32_t a2,
                                       uint32_t a3, uint32_t b0, uint32_t b1){
    asm volatile("mma.sync.aligned.m16n8k16.row.col.f16.f16.f16.f16 "
        "{%0,%1}, {%2,%3,%4,%5}, {%6,%7}, {%0,%1};"
        : "+r"(c0), "+r"(c1)
        : "r"(a0), "r"(a1), "r"(a2), "r"(a3), "r"(b0), "r"(b1));
}

// cp.async 16B with L1 allocation (.ca — reused tiles hit L1), commit, wait
#define CP16(dst_u32, src_ptr) \
    asm volatile("cp.async.ca.shared.global [%0], [%1], 16;" \
        :: "r"(dst_u32), "l"(src_ptr) : "memory")
#define CP_COMMIT() asm volatile("cp.async.commit_group;" ::: "memory")
#define CP_WAIT0()  asm volatile("cp.async.wait_group 0;" ::: "memory")

// Pair-interleaved group format (GLOBAL + SMEM): a 16-half k-group is stored
// as uint pairs in order {p01,p89,p23,p1011,p45,p1213,p67,p1415}; pair j ->
// uint slot ILVu(j) = j<4 ? 2j : 2(j-4)+1. Matches the fragment pairing the
// LDS.64 loads expect. Loaders are pure 16B cp.async copies.
__device__ __forceinline__ int ilvu(int j){ return (j < 4) ? 2 * j : 2 * (j - 4) + 1; }

// SMEM tile addressing, padded non-wrapping swizzle (affine in row,kb):
#define KB_STRIDE  2176
#define HALF_TILE  8704                     // 4 * KB_STRIDE
__device__ __forceinline__ uint32_t grp_off(int row, int kb){
    return ((row >> 6) * HALF_TILE) + kb * KB_STRIDE + (((row & 63) + kb) << 5);
}
__device__ __forceinline__ uint32_t grp_off64(int j, int kb){
    return kb * KB_STRIDE + ((j + kb) << 5);
}

// ---------------- f32 -> f16 conversion pre-pass (emits interleaved) ----------------
__global__ __launch_bounds__(256) void cvt_f16(
    const float* __restrict__ q, const float* __restrict__ k,
    const float* __restrict__ v,
    const float* __restrict__ Wq, const float* __restrict__ Wk,
    const float* __restrict__ Wv, const float* __restrict__ Wo)
{
    const int z = blockIdx.z;
    const float* src; __half* dst; int n;
    if (z < 3) {
        src = (z == 0) ? q : (z == 1) ? k : v;
        dst = (__half*)(g_scr + OFF_QF + (size_t)z * 8 * MB_);
        n = M_ * D_;
    } else {
        src = (z == 3) ? Wq : (z == 4) ? Wk : (z == 5) ? Wv : Wo;
        dst = (__half*)(g_scr + OFF_WF + (size_t)(z - 3) * 512 * 1024);
        n = D_ * D_;
    }
    int i = (blockIdx.x * 256 + threadIdx.x) * 16;
    if (i >= n) return;
    float4 c0 = *(const float4*)&src[i];
    float4 c1 = *(const float4*)&src[i + 4];
    float4 c2 = *(const float4*)&src[i + 8];
    float4 c3 = *(const float4*)&src[i + 12];
    // interleaved: {p01,p89,p23,p1011 | p45,p1213,p67,p1415}
    *(uint4*)&dst[i]     = make_uint4(packh2(c0.x,c0.y), packh2(c2.x,c2.y),
                                      packh2(c0.z,c0.w), packh2(c2.z,c2.w));
    *(uint4*)&dst[i + 8] = make_uint4(packh2(c1.x,c1.y), packh2(c3.x,c3.y),
                                      packh2(c1.z,c1.w), packh2(c3.z,c3.w));
}

// ---------------- projection GEMMs (cp.async.ca loaders, f16 mma, BM=128 BN=128) ----------------
#define PJ_A_BYTES (2 * HALF_TILE)               // 17408
#define PJ_W_BYTES (2 * HALF_TILE)               // 17408
#define PJ_BUF_BYTES (PJ_A_BYTES + PJ_W_BYTES)   // 34816
#define PJ_SMEM (2 * PJ_BUF_BYTES)               // 69632

// QKV projection: blockIdx.z selects {q->GQ(natural), k->GK(ilv), v->GVT(ilv,transposed)}
__global__ __launch_bounds__(256, 2) void proj_qkv(float qscale)
{
    extern __shared__ char smc[];
    const int z = blockIdx.z;
    const __half* A = (const __half*)(g_scr + OFF_QF + (size_t)z * 8 * MB_);
    const __half* W = (const __half*)(g_scr + OFF_WF + (size_t)z * 512 * 1024);
    __half* out = (__half*)(g_scr + (size_t)z * 8 * MB_);
    const float scale = (z == 0) ? qscale : 1.0f;

    const int tid = threadIdx.x, lane = tid & 31, w = tid >> 5;
    const int wr = w >> 1, wc = w & 1;               // 4 x 2 warp grid
    const int qq = lane >> 2, t = lane & 3;
    const int m0 = blockIdx.y * 128, n0 = blockIdx.x * 128;
    const uint32_t smem_u = (uint32_t)__cvta_generic_to_shared(smc);

    auto load_chunk = [&](int ch){
        const int k0 = ch * 64, bsel = ch & 1;
        const uint32_t abuf = smem_u + bsel * PJ_BUF_BYTES;
        const uint32_t wbuf = abuf + PJ_A_BYTES;
        #pragma unroll
        for (int i = 0; i < 2; i++) {
            int u = tid + i * 256;
            int kb = u & 3, row = u >> 2;             // [0,128)
            const __half* sa = &A[(size_t)(m0 + row) * 512 + k0 + kb * 16];
            const __half* sw = &W[(size_t)(n0 + row) * 512 + k0 + kb * 16];
            uint32_t da = abuf + grp_off(row, kb);
            uint32_t dw = wbuf + grp_off(row, kb);
            CP16(da, sa); CP16(da + 16, sa + 8);
            CP16(dw, sw); CP16(dw + 16, sw + 8);
        }
    };

    float c[2][8][4] = {};
    load_chunk(0); CP_COMMIT();

    for (int ch = 0; ch < 8; ch++) {
        CP_WAIT0();
        __syncthreads();
        if (ch < 7) { load_chunk(ch + 1); CP_COMMIT(); }
        const char* abuf = smc + (ch & 1) * PJ_BUF_BYTES;
        const char* wbuf = abuf + PJ_A_BYTES;

        #pragma unroll
        for (int kb = 0; kb < 4; kb++) {
            uint2 af[2][2];
            #pragma unroll
            for (int blk = 0; blk < 2; blk++) {
                int r = wr * 32 + blk * 16 + qq;
                af[blk][0] = *(const uint2*)(abuf + grp_off(r,     kb) + t * 8);
                af[blk][1] = *(const uint2*)(abuf + grp_off(r + 8, kb) + t * 8);
            }
            #pragma unroll
            for (int ni = 0; ni < 8; ni++) {
                uint2 b = *(const uint2*)(wbuf + grp_off(wc * 64 + ni * 8 + qq, kb) + t * 8);
                mma16(c[0][ni], af[0][0].x, af[0][1].x, af[0][0].y, af[0][1].y, b.x, b.y);
                mma16(c[1][ni], af[1][0].x, af[1][1].x, af[1][0].y, af[1][1].y, b.x, b.y);
            }
        }
    }

    const int h = (n0 >> 6) + wc;                    // 64-col warp block = one head
    #pragma unroll
    for (int blk = 0; blk < 2; blk++)
        #pragma unroll
        for (int ni = 0; ni < 8; ni++) {
            // natural column (z==0) vs interleaved column (z==1)
            const int dkc_nat = ni * 8 + 2 * t;
            const int dkc_ilv = (ni >> 1) * 16 + 4 * t + 2 * (ni & 1);
            #pragma unroll
            for (int h2 = 0; h2 < 2; h2++) {
                int m = m0 + wr * 32 + blk * 16 + qq + h2 * 8;
                int b = m >> 12, s = m & 4095;
                float v0 = c[blk][ni][h2 * 2 + 0] * scale;
                float v1 = c[blk][ni][h2 * 2 + 1] * scale;
                if (z < 2) {
                    int dkc = (z == 0) ? dkc_nat : dkc_ilv;
                    *(__half2*)(out + ((size_t)(b * H_ + h) * S_ + s) * DK_ + dkc)
                        = __floats2half2_rn(v0, v1);
                } else {
                    // gVT: interleave along s within 16-groups
                    int sl = s & 15;
                    int s_ilv = (s & ~15) + 2 * ilvu(sl >> 1) + (sl & 1);
                    out[((size_t)(b * H_ + h) * DK_ + dkc_nat    ) * S_ + s_ilv] = __float2half(v0);
                    out[((size_t)(b * H_ + h) * DK_ + dkc_nat + 1) * S_ + s_ilv] = __float2half(v1);
                }
            }
        }
}

// Output projection: GOH (ilv) gathered @ Wo^T (ilv) -> f32 out
__global__ __launch_bounds__(256, 2) void proj_out(float* __restrict__ Cout)
{
    extern __shared__ char smc[];
    const __half* Agat = (const __half*)(g_scr + OFF_GOH);
    const __half* W    = (const __half*)(g_scr + OFF_WF + 3 * 512 * 1024);

    const int tid = threadIdx.x, lane = tid & 31, w = tid >> 5;
    const int wr = w >> 1, wc = w & 1;
    const int qq = lane >> 2, t = lane & 3;
    const int m0 = blockIdx.y * 128, n0 = blockIdx.x * 128;
    const uint32_t smem_u = (uint32_t)__cvta_generic_to_shared(smc);

    auto load_chunk = [&](int ch){
        const int k0 = ch * 64, bsel = ch & 1;
        const uint32_t abuf = smem_u + bsel * PJ_BUF_BYTES;
        const uint32_t wbuf = abuf + PJ_A_BYTES;
        #pragma unroll
        for (int i = 0; i < 2; i++) {
            int u = tid + i * 256;
            int kb = u & 3, row = u >> 2;
            int m = m0 + row, b = m >> 12, s = m & 4095;
            const __half* sa = &Agat[((size_t)(b * H_ + ch) * S_ + s) * DK_ + kb * 16];
            const __half* sw = &W[(size_t)(n0 + row) * 512 + k0 + kb * 16];
            uint32_t da = abuf + grp_off(row, kb);
            uint32_t dw = wbuf + grp_off(row, kb);
            CP16(da, sa); CP16(da + 16, sa + 8);
            CP16(dw, sw); CP16(dw + 16, sw + 8);
        }
    };

    float c[2][8][4] = {};
    load_chunk(0); CP_COMMIT();

    for (int ch = 0; ch < 8; ch++) {
        CP_WAIT0();
        __syncthreads();
        if (ch < 7) { load_chunk(ch + 1); CP_COMMIT(); }
        const char* abuf = smc + (ch & 1) * PJ_BUF_BYTES;
        const char* wbuf = abuf + PJ_A_BYTES;

        #pragma unroll
        for (int kb = 0; kb < 4; kb++) {
            uint2 af[2][2];
            #pragma unroll
            for (int blk = 0; blk < 2; blk++) {
                int r = wr * 32 + blk * 16 + qq;
                af[blk][0] = *(const uint2*)(abuf + grp_off(r,     kb) + t * 8);
                af[blk][1] = *(const uint2*)(abuf + grp_off(r + 8, kb) + t * 8);
            }
            #pragma unroll
            for (int ni = 0; ni < 8; ni++) {
                uint2 b = *(const uint2*)(wbuf + grp_off(wc * 64 + ni * 8 + qq, kb) + t * 8);
                mma16(c[0][ni], af[0][0].x, af[0][1].x, af[0][0].y, af[0][1].y, b.x, b.y);
                mma16(c[1][ni], af[1][0].x, af[1][1].x, af[1][0].y, af[1][1].y, b.x, b.y);
            }
        }
    }

    #pragma unroll
    for (int blk = 0; blk < 2; blk++)
        #pragma unroll
        for (int ni = 0; ni < 8; ni++)
            #pragma unroll
            for (int h2 = 0; h2 < 2; h2++) {
                int m = m0 + wr * 32 + blk * 16 + qq + h2 * 8;
                int n = n0 + wc * 64 + ni * 8 + 2 * t;
                *(float2*)&Cout[(size_t)m * 512 + n] =
                    make_float2(c[blk][ni][h2 * 2 + 0], c[blk][ni][h2 * 2 + 1]);
            }
}

// ---------------- attention (cp.async.ca loader; f16 S-accum + mask bias) ----------------
#define KF_BYTES  (4 * KB_STRIDE)           // 8704
#define VF_BYTES  (4 * KB_STRIDE)           // 8704
#define BUF_BYTES (KF_BYTES + VF_BYTES)     // 17408
#define SM_BUF0   1024
#define ATT_SMEM  (SM_BUF0 + 2 * BUF_BYTES) // 35840

__global__ __launch_bounds__(128, 3) void attn_kernel(const int* __restrict__ mask)
{
    extern __shared__ char smc[];
    __half* maskh = (__half*)smc;           // [2][64] additive bias: 0 or -30000

    const int tid = threadIdx.x, lane = tid & 31, w = tid >> 5;
    const int q = lane >> 2, t = lane & 3;
    const int bh = blockIdx.y, bb = bh >> 3;
    const int q0 = blockIdx.x * 128;
    const uint32_t smem_u = (uint32_t)__cvta_generic_to_shared(smc);

    const __half* gQh  = (const __half*)(g_scr + OFF_GQ);
    const __half* gKh  = (const __half*)(g_scr + OFF_GK);
    const __half* gVTh = (const __half*)(g_scr + OFF_GVT);
    __half*       gOh  = (__half*)(g_scr + OFF_GOH);
    const size_t base    = (size_t)bh * S_ * DK_;
    const size_t vt_base = (size_t)bh * DK_ * S_;

    // ---- Q fragments from gQ (natural layout), loop-invariant ----
    const int r0 = w * 32 + q;
    uint32_t qa[2][4][4];
    #pragma unroll
    for (int blk = 0; blk < 2; blk++) {
        const __half* qp = gQh + base + (size_t)(q0 + r0 + blk * 16) * DK_;
        #pragma unroll
        for (int kb = 0; kb < 4; kb++) {
            qa[blk][kb][0] = *(const uint32_t*)(qp + kb * 16 + 2 * t);
            qa[blk][kb][1] = *(const uint32_t*)(qp + 8 * DK_ + kb * 16 + 2 * t);
            qa[blk][kb][2] = *(const uint32_t*)(qp + kb * 16 + 2 * t + 8);
            qa[blk][kb][3] = *(const uint32_t*)(qp + 8 * DK_ + kb * 16 + 2 * t + 8);
        }
    }

    auto load_tile = [&](int it) {
        const int n0 = it * 64, bsel = it & 1;
        const uint32_t kbuf = smem_u + SM_BUF0 + bsel * BUF_BYTES;
        const uint32_t vbuf = kbuf + KF_BYTES;
        #pragma unroll
        for (int i = 0; i < 2; i++) {
            int u = tid + i * 128;
            int kb = u & 3, j = u >> 2;               // j in [0,64)
            const __half* sk = gKh + base + (size_t)(n0 + j) * DK_ + kb * 16;
            const __half* sv = gVTh + vt_base + (size_t)j * S_ + n0 + kb * 16;
            uint32_t dk = kbuf + grp_off64(j, kb);
            uint32_t dv = vbuf + grp_off64(j, kb);
            CP16(dk, sk); CP16(dk + 16, sk + 8);
            CP16(dv, sv); CP16(dv + 16, sv + 8);
        }
        if (tid < 64)
            maskh[bsel * 64 + tid] =
                __float2half(mask[bb * S_ + n0 + tid] ? 0.f : -30000.f);
    };

    float o[2][8][4] = {};
    float ol[2][4] = {};                    // ones-column accumulators (l)

    load_tile(0); CP_COMMIT();

    for (int it = 0; it < 64; it++) {
        CP_WAIT0();
        __syncthreads();
        if (it < 63) { load_tile(it + 1); CP_COMMIT(); }

        const int bsel = it & 1;
        const char* kbuf = smc + SM_BUF0 + bsel * BUF_BYTES;
        const char* vbuf = kbuf + KF_BYTES;
        const __half* mb = maskh + bsel * 64;

        // ---- S = mask_bias + Q @ K^T  (f16 accumulators) ----
        uint32_t s[2][8][2];
        #pragma unroll
        for (int ni = 0; ni < 8; ni++) {
            uint32_t m2 = *(const uint32_t*)(mb + ni * 8 + 2 * t);
            s[0][ni][0] = m2; s[0][ni][1] = m2;
            s[1][ni][0] = m2; s[1][ni][1] = m2;
        }
        #pragma unroll
        for (int kb = 0; kb < 4; kb++) {
            const char* kp = kbuf + kb * KB_STRIDE + (q + kb) * 32 + t * 8;
            #pragma unroll
            for (int ni = 0; ni < 8; ni++) {
                uint2 b = *(const uint2*)(kp + ni * 256);
                mma16h(s[0][ni][0], s[0][ni][1],
                       qa[0][kb][0], qa[0][kb][1], qa[0][kb][2], qa[0][kb][3], b.x, b.y);
                mma16h(s[1][ni][0], s[1][ni][1],
                       qa[1][kb][0], qa[1][kb][1], qa[1][kb][2], qa[1][kb][3], b.x, b.y);
            }
        }

        // ---- softmax: p = ex2(s) in place; s IS the PV A-fragment set ----
        #pragma unroll
        for (int ni = 0; ni < 8; ni++) {
            s[0][ni][0] = ex2h2(s[0][ni][0]); s[0][ni][1] = ex2h2(s[0][ni][1]);
            s[1][ni][0] = ex2h2(s[1][ni][0]); s[1][ni][1] = ex2h2(s[1][ni][1]);
        }

        // ---- O += P @ V, plus ones-column for l ----
        #pragma unroll
        for (int jb = 0; jb < 4; jb++) {
            const char* vp = vbuf + jb * KB_STRIDE + (q + jb) * 32 + t * 8;
            #pragma unroll
            for (int ni = 0; ni < 8; ni++) {
                uint2 b = *(const uint2*)(vp + ni * 256);
                mma16(o[0][ni], s[0][2*jb][0], s[0][2*jb][1],
                                s[0][2*jb+1][0], s[0][2*jb+1][1], b.x, b.y);
                mma16(o[1][ni], s[1][2*jb][0], s[1][2*jb][1],
                                s[1][2*jb+1][0], s[1][2*jb+1][1], b.x, b.y);
            }
            mma16(ol[0], s[0][2*jb][0], s[0][2*jb][1],
                         s[0][2*jb+1][0], s[0][2*jb+1][1], ONES_H2, ONES_H2);
            mma16(ol[1], s[1][2*jb][0], s[1][2*jb][1],
                         s[1][2*jb+1][0], s[1][2*jb+1][1], ONES_H2, ONES_H2);
        }
    }

    // ---- finalize: normalize + write GOH in interleaved format ----
    #pragma unroll
    for (int blk = 0; blk < 2; blk++) {
        const float l0 = ol[blk][0], l1 = ol[blk][2];
        const float inv0 = (l0 > 0.f) ? (1.f / l0) : 0.f;
        const float inv1 = (l1 > 0.f) ? (1.f / l1) : 0.f;
        const int rr = q0 + r0 + blk * 16;
        #pragma unroll
        for (int ni = 0; ni < 8; ni++) {
            int col = (ni >> 1) * 16 + 4 * t + 2 * (ni & 1);   // interleaved
            *(__half2*)(gOh + base + (size_t)(rr    ) * DK_ + col) =
                __floats2half2_rn(o[blk][ni][0] * inv0, o[blk][ni][1] * inv0);
            *(__half2*)(gOh + base + (size_t)(rr + 8) * DK_ + col) =
                __floats2half2_rn(o[blk][ni][2] * inv1, o[blk][ni][3] * inv1);
        }
    }
}

// ---------------- launch ----------------
extern "C" void kernel_launch(void* const* d_in, const int* in_sizes, int n_in,
                              void* d_out, int out_size)
{
    const float* q    = (const float*)d_in[0];
    const float* k    = (const float*)d_in[1];
    const float* v    = (const float*)d_in[2];
    const int*   mask = (const int*)  d_in[3];
    const float* Wq   = (const float*)d_in[4];
    const float* Wk   = (const float*)d_in[5];
    const float* Wv   = (const float*)d_in[6];
    const float* Wo   = (const float*)d_in[7];
    float* out = (float*)d_out;

    cudaFuncSetAttribute(attn_kernel,
                         cudaFuncAttributeMaxDynamicSharedMemorySize, ATT_SMEM);
    cudaFuncSetAttribute(proj_qkv,
                         cudaFuncAttributeMaxDynamicSharedMemorySize, PJ_SMEM);
    cudaFuncSetAttribute(proj_out,
                         cudaFuncAttributeMaxDynamicSharedMemorySize, PJ_SMEM);

    // fold 1/sqrt(DK) * log2(e) into Q so attention works in exp2 domain
    const float qscale = 0.125f * 1.4426950408889634f;

    cvt_f16<<<dim3((M_ * D_) / (256 * 16), 1, 7), 256>>>(q, k, v, Wq, Wk, Wv, Wo);
    proj_qkv<<<dim3(D_ / 128, M_ / 128, 3), 256, PJ_SMEM>>>(qscale);
    attn_kernel<<<dim3(S_ / 128, B_ * H_), 128, ATT_SMEM>>>(mask);
    proj_out<<<dim3(D_ / 128, M_ / 128), 256, PJ_SMEM>>>(out);
}

// round 16
// speedup vs baseline: 1.4631x; 1.0532x over previous
#include <cuda_runtime.h>
#include <cuda_fp16.h>
#include <cstdint>

#define B_  2
#define S_  4096
#define D_  512
#define H_  8
#define DK_ 64
#define M_  (B_*S_)   // 8192

// Byte-offset scratch map:
//  GQ 0MB (f16 natural), GK 8MB (f16 ilv), GVT 16MB (f16 ilv along s),
//  GOH 24MB (f16 ilv, combined attn out),
//  QF 32MB, KF 40MB, VF 48MB (cvt inputs, ilv), WF 56MB (4x 512KB weights, ilv)
//  OP0 58MB, OP1 74MB (f32 unnormalized O partials, 16MB each)
//  LP 90MB (f32 l partials, 2 x 64K rows)
#define MB_ (1024*1024)
#define OFF_GQ   0
#define OFF_GK   (8*MB_)
#define OFF_GVT  (16*MB_)
#define OFF_GOH  (24*MB_)
#define OFF_QF   (32*MB_)
#define OFF_WF   (56*MB_)
#define OFF_OP0  (58*MB_)
#define OFF_OP1  (74*MB_)
#define OFF_LP   (90*MB_)
__device__ __align__(16) unsigned char g_scr[91 * MB_];

#define ONES_H2 0x3C003C00u

// ---------------- helpers ----------------
__device__ __forceinline__ uint32_t packh2(float lo, float hi){
    uint32_t u; asm("cvt.rn.f16x2.f32 %0, %1, %2;" : "=r"(u) : "f"(hi), "f"(lo));
    return u;
}
__device__ __forceinline__ uint32_t ex2h2(uint32_t x){
    uint32_t r; asm("ex2.approx.f16x2 %0, %1;" : "=r"(r) : "r"(x)); return r;
}
__device__ __forceinline__ void mma16(float* c, uint32_t a0, uint32_t a1, uint32_t a2,
                                      uint32_t a3, uint32_t b0, uint32_t b1){
    asm volatile("mma.sync.aligned.m16n8k16.row.col.f32.f16.f16.f32 "
        "{%0,%1,%2,%3}, {%4,%5,%6,%7}, {%8,%9}, {%0,%1,%2,%3};"
        : "+f"(c[0]), "+f"(c[1]), "+f"(c[2]), "+f"(c[3])
        : "r"(a0), "r"(a1), "r"(a2), "r"(a3), "r"(b0), "r"(b1));
}
__device__ __forceinline__ void mma16h(uint32_t& c0, uint32_t& c1,
                                       uint32_t a0, uint32_t a1, uint32_t a2,
                                       uint32_t a3, uint32_t b0, uint32_t b1){
    asm volatile("mma.sync.aligned.m16n8k16.row.col.f16.f16.f16.f16 "
        "{%0,%1}, {%2,%3,%4,%5}, {%6,%7}, {%0,%1};"
        : "+r"(c0), "+r"(c1)
        : "r"(a0), "r"(a1), "r"(a2), "r"(a3), "r"(b0), "r"(b1));
}

// cp.async 16B with L1 allocation (.ca — reused tiles hit L1), commit, wait
#define CP16(dst_u32, src_ptr) \
    asm volatile("cp.async.ca.shared.global [%0], [%1], 16;" \
        :: "r"(dst_u32), "l"(src_ptr) : "memory")
#define CP_COMMIT() asm volatile("cp.async.commit_group;" ::: "memory")
#define CP_WAIT0()  asm volatile("cp.async.wait_group 0;" ::: "memory")

// Pair-interleaved group format (GLOBAL + SMEM), see R14/R15.
__device__ __forceinline__ int ilvu(int j){ return (j < 4) ? 2 * j : 2 * (j - 4) + 1; }

// SMEM tile addressing, padded non-wrapping swizzle (affine in row,kb):
#define KB_STRIDE  2176
#define HALF_TILE  8704                     // 4 * KB_STRIDE
__device__ __forceinline__ uint32_t grp_off(int row, int kb){
    return ((row >> 6) * HALF_TILE) + kb * KB_STRIDE + (((row & 63) + kb) << 5);
}
__device__ __forceinline__ uint32_t grp_off64(int j, int kb){
    return kb * KB_STRIDE + ((j + kb) << 5);
}

// ---------------- f32 -> f16 conversion pre-pass (emits interleaved) ----------------
__global__ __launch_bounds__(256) void cvt_f16(
    const float* __restrict__ q, const float* __restrict__ k,
    const float* __restrict__ v,
    const float* __restrict__ Wq, const float* __restrict__ Wk,
    const float* __restrict__ Wv, const float* __restrict__ Wo)
{
    const int z = blockIdx.z;
    const float* src; __half* dst; int n;
    if (z < 3) {
        src = (z == 0) ? q : (z == 1) ? k : v;
        dst = (__half*)(g_scr + OFF_QF + (size_t)z * 8 * MB_);
        n = M_ * D_;
    } else {
        src = (z == 3) ? Wq : (z == 4) ? Wk : (z == 5) ? Wv : Wo;
        dst = (__half*)(g_scr + OFF_WF + (size_t)(z - 3) * 512 * 1024);
        n = D_ * D_;
    }
    int i = (blockIdx.x * 256 + threadIdx.x) * 16;
    if (i >= n) return;
    float4 c0 = *(const float4*)&src[i];
    float4 c1 = *(const float4*)&src[i + 4];
    float4 c2 = *(const float4*)&src[i + 8];
    float4 c3 = *(const float4*)&src[i + 12];
    *(uint4*)&dst[i]     = make_uint4(packh2(c0.x,c0.y), packh2(c2.x,c2.y),
                                      packh2(c0.z,c0.w), packh2(c2.z,c2.w));
    *(uint4*)&dst[i + 8] = make_uint4(packh2(c1.x,c1.y), packh2(c3.x,c3.y),
                                      packh2(c1.z,c1.w), packh2(c3.z,c3.w));
}

// ---------------- projection GEMMs (cp.async.ca loaders, f16 mma, BM=128 BN=128) ----------------
#define PJ_A_BYTES (2 * HALF_TILE)               // 17408
#define PJ_W_BYTES (2 * HALF_TILE)               // 17408
#define PJ_BUF_BYTES (PJ_A_BYTES + PJ_W_BYTES)   // 34816
#define PJ_SMEM (2 * PJ_BUF_BYTES)               // 69632

// QKV projection: blockIdx.z selects {q->GQ(natural), k->GK(ilv), v->GVT(ilv,transposed)}
__global__ __launch_bounds__(256, 2) void proj_qkv(float qscale)
{
    extern __shared__ char smc[];
    const int z = blockIdx.z;
    const __half* A = (const __half*)(g_scr + OFF_QF + (size_t)z * 8 * MB_);
    const __half* W = (const __half*)(g_scr + OFF_WF + (size_t)z * 512 * 1024);
    __half* out = (__half*)(g_scr + (size_t)z * 8 * MB_);
    const float scale = (z == 0) ? qscale : 1.0f;

    const int tid = threadIdx.x, lane = tid & 31, w = tid >> 5;
    const int wr = w >> 1, wc = w & 1;               // 4 x 2 warp grid
    const int qq = lane >> 2, t = lane & 3;
    const int m0 = blockIdx.y * 128, n0 = blockIdx.x * 128;
    const uint32_t smem_u = (uint32_t)__cvta_generic_to_shared(smc);

    auto load_chunk = [&](int ch){
        const int k0 = ch * 64, bsel = ch & 1;
        const uint32_t abuf = smem_u + bsel * PJ_BUF_BYTES;
        const uint32_t wbuf = abuf + PJ_A_BYTES;
        #pragma unroll
        for (int i = 0; i < 2; i++) {
            int u = tid + i * 256;
            int kb = u & 3, row = u >> 2;             // [0,128)
            const __half* sa = &A[(size_t)(m0 + row) * 512 + k0 + kb * 16];
            const __half* sw = &W[(size_t)(n0 + row) * 512 + k0 + kb * 16];
            uint32_t da = abuf + grp_off(row, kb);
            uint32_t dw = wbuf + grp_off(row, kb);
            CP16(da, sa); CP16(da + 16, sa + 8);
            CP16(dw, sw); CP16(dw + 16, sw + 8);
        }
    };

    float c[2][8][4] = {};
    load_chunk(0); CP_COMMIT();

    for (int ch = 0; ch < 8; ch++) {
        CP_WAIT0();
        __syncthreads();
        if (ch < 7) { load_chunk(ch + 1); CP_COMMIT(); }
        const char* abuf = smc + (ch & 1) * PJ_BUF_BYTES;
        const char* wbuf = abuf + PJ_A_BYTES;

        #pragma unroll
        for (int kb = 0; kb < 4; kb++) {
            uint2 af[2][2];
            #pragma unroll
            for (int blk = 0; blk < 2; blk++) {
                int r = wr * 32 + blk * 16 + qq;
                af[blk][0] = *(const uint2*)(abuf + grp_off(r,     kb) + t * 8);
                af[blk][1] = *(const uint2*)(abuf + grp_off(r + 8, kb) + t * 8);
            }
            #pragma unroll
            for (int ni = 0; ni < 8; ni++) {
                uint2 b = *(const uint2*)(wbuf + grp_off(wc * 64 + ni * 8 + qq, kb) + t * 8);
                mma16(c[0][ni], af[0][0].x, af[0][1].x, af[0][0].y, af[0][1].y, b.x, b.y);
                mma16(c[1][ni], af[1][0].x, af[1][1].x, af[1][0].y, af[1][1].y, b.x, b.y);
            }
        }
    }

    const int h = (n0 >> 6) + wc;                    // 64-col warp block = one head
    #pragma unroll
    for (int blk = 0; blk < 2; blk++)
        #pragma unroll
        for (int ni = 0; ni < 8; ni++) {
            const int dkc_nat = ni * 8 + 2 * t;
            const int dkc_ilv = (ni >> 1) * 16 + 4 * t + 2 * (ni & 1);
            #pragma unroll
            for (int h2 = 0; h2 < 2; h2++) {
                int m = m0 + wr * 32 + blk * 16 + qq + h2 * 8;
                int b = m >> 12, s = m & 4095;
                float v0 = c[blk][ni][h2 * 2 + 0] * scale;
                float v1 = c[blk][ni][h2 * 2 + 1] * scale;
                if (z < 2) {
                    int dkc = (z == 0) ? dkc_nat : dkc_ilv;
                    *(__half2*)(out + ((size_t)(b * H_ + h) * S_ + s) * DK_ + dkc)
                        = __floats2half2_rn(v0, v1);
                } else {
                    int sl = s & 15;
                    int s_ilv = (s & ~15) + 2 * ilvu(sl >> 1) + (sl & 1);
                    out[((size_t)(b * H_ + h) * DK_ + dkc_nat    ) * S_ + s_ilv] = __float2half(v0);
                    out[((size_t)(b * H_ + h) * DK_ + dkc_nat + 1) * S_ + s_ilv] = __float2half(v1);
                }
            }
        }
}

// Output projection: GOH (ilv) gathered @ Wo^T (ilv) -> f32 out
__global__ __launch_bounds__(256, 2) void proj_out(float* __restrict__ Cout)
{
    extern __shared__ char smc[];
    const __half* Agat = (const __half*)(g_scr + OFF_GOH);
    const __half* W    = (const __half*)(g_scr + OFF_WF + 3 * 512 * 1024);

    const int tid = threadIdx.x, lane = tid & 31, w = tid >> 5;
    const int wr = w >> 1, wc = w & 1;
    const int qq = lane >> 2, t = lane & 3;
    const int m0 = blockIdx.y * 128, n0 = blockIdx.x * 128;
    const uint32_t smem_u = (uint32_t)__cvta_generic_to_shared(smc);

    auto load_chunk = [&](int ch){
        const int k0 = ch * 64, bsel = ch & 1;
        const uint32_t abuf = smem_u + bsel * PJ_BUF_BYTES;
        const uint32_t wbuf = abuf + PJ_A_BYTES;
        #pragma unroll
        for (int i = 0; i < 2; i++) {
            int u = tid + i * 256;
            int kb = u & 3, row = u >> 2;
            int m = m0 + row, b = m >> 12, s = m & 4095;
            const __half* sa = &Agat[((size_t)(b * H_ + ch) * S_ + s) * DK_ + kb * 16];
            const __half* sw = &W[(size_t)(n0 + row) * 512 + k0 + kb * 16];
            uint32_t da = abuf + grp_off(row, kb);
            uint32_t dw = wbuf + grp_off(row, kb);
            CP16(da, sa); CP16(da + 16, sa + 8);
            CP16(dw, sw); CP16(dw + 16, sw + 8);
        }
    };

    float c[2][8][4] = {};
    load_chunk(0); CP_COMMIT();

    for (int ch = 0; ch < 8; ch++) {
        CP_WAIT0();
        __syncthreads();
        if (ch < 7) { load_chunk(ch + 1); CP_COMMIT(); }
        const char* abuf = smc + (ch & 1) * PJ_BUF_BYTES;
        const char* wbuf = abuf + PJ_A_BYTES;

        #pragma unroll
        for (int kb = 0; kb < 4; kb++) {
            uint2 af[2][2];
            #pragma unroll
            for (int blk = 0; blk < 2; blk++) {
                int r = wr * 32 + blk * 16 + qq;
                af[blk][0] = *(const uint2*)(abuf + grp_off(r,     kb) + t * 8);
                af[blk][1] = *(const uint2*)(abuf + grp_off(r + 8, kb) + t * 8);
            }
            #pragma unroll
            for (int ni = 0; ni < 8; ni++) {
                uint2 b = *(const uint2*)(wbuf + grp_off(wc * 64 + ni * 8 + qq, kb) + t * 8);
                mma16(c[0][ni], af[0][0].x, af[0][1].x, af[0][0].y, af[0][1].y, b.x, b.y);
                mma16(c[1][ni], af[1][0].x, af[1][1].x, af[1][0].y, af[1][1].y, b.x, b.y);
            }
        }
    }

    #pragma unroll
    for (int blk = 0; blk < 2; blk++)
        #pragma unroll
        for (int ni = 0; ni < 8; ni++)
            #pragma unroll
            for (int h2 = 0; h2 < 2; h2++) {
                int m = m0 + wr * 32 + blk * 16 + qq + h2 * 8;
                int n = n0 + wc * 64 + ni * 8 + 2 * t;
                *(float2*)&Cout[(size_t)m * 512 + n] =
                    make_float2(c[blk][ni][h2 * 2 + 0], c[blk][ni][h2 * 2 + 1]);
            }
}

// ---------------- attention (split-KV x2; f16 S-accum + mask bias) ----------------
// CTA = 128 q rows x 32 kv tiles (blockIdx.z = kv half). Writes UNNORMALIZED
// f32 O-partials + l partials; combine kernel merges the halves.
#define KF_BYTES  (4 * KB_STRIDE)           // 8704
#define VF_BYTES  (4 * KB_STRIDE)           // 8704
#define BUF_BYTES (KF_BYTES + VF_BYTES)     // 17408
#define SM_BUF0   1024
#define ATT_SMEM  (SM_BUF0 + 2 * BUF_BYTES) // 35840

__global__ __launch_bounds__(128, 3) void attn_kernel(const int* __restrict__ mask)
{
    extern __shared__ char smc[];
    __half* maskh = (__half*)smc;           // [2][64] additive bias: 0 or -30000

    const int tid = threadIdx.x, lane = tid & 31, w = tid >> 5;
    const int q = lane >> 2, t = lane & 3;
    const int bh = blockIdx.y, bb = bh >> 3;
    const int q0 = blockIdx.x * 128;
    const int z  = blockIdx.z;              // kv half
    const int it0 = z * 32, it1 = it0 + 32;
    const uint32_t smem_u = (uint32_t)__cvta_generic_to_shared(smc);

    const __half* gQh  = (const __half*)(g_scr + OFF_GQ);
    const __half* gKh  = (const __half*)(g_scr + OFF_GK);
    const __half* gVTh = (const __half*)(g_scr + OFF_GVT);
    float* gOp = (float*)(g_scr + (z == 0 ? OFF_OP0 : OFF_OP1));
    float* gLp = (float*)(g_scr + OFF_LP) + (size_t)z * (B_ * H_ * S_);
    const size_t base    = (size_t)bh * S_ * DK_;
    const size_t vt_base = (size_t)bh * DK_ * S_;

    // ---- Q fragments from gQ (natural layout), loop-invariant ----
    const int r0 = w * 32 + q;
    uint32_t qa[2][4][4];
    #pragma unroll
    for (int blk = 0; blk < 2; blk++) {
        const __half* qp = gQh + base + (size_t)(q0 + r0 + blk * 16) * DK_;
        #pragma unroll
        for (int kb = 0; kb < 4; kb++) {
            qa[blk][kb][0] = *(const uint32_t*)(qp + kb * 16 + 2 * t);
            qa[blk][kb][1] = *(const uint32_t*)(qp + 8 * DK_ + kb * 16 + 2 * t);
            qa[blk][kb][2] = *(const uint32_t*)(qp + kb * 16 + 2 * t + 8);
            qa[blk][kb][3] = *(const uint32_t*)(qp + 8 * DK_ + kb * 16 + 2 * t + 8);
        }
    }

    auto load_tile = [&](int it) {
        const int n0 = it * 64, bsel = it & 1;
        const uint32_t kbuf = smem_u + SM_BUF0 + bsel * BUF_BYTES;
        const uint32_t vbuf = kbuf + KF_BYTES;
        #pragma unroll
        for (int i = 0; i < 2; i++) {
            int u = tid + i * 128;
            int kb = u & 3, j = u >> 2;               // j in [0,64)
            const __half* sk = gKh + base + (size_t)(n0 + j) * DK_ + kb * 16;
            const __half* sv = gVTh + vt_base + (size_t)j * S_ + n0 + kb * 16;
            uint32_t dk = kbuf + grp_off64(j, kb);
            uint32_t dv = vbuf + grp_off64(j, kb);
            CP16(dk, sk); CP16(dk + 16, sk + 8);
            CP16(dv, sv); CP16(dv + 16, sv + 8);
        }
        if (tid < 64)
            maskh[(it & 1) * 64 + tid] =
                __float2half(mask[bb * S_ + n0 + tid] ? 0.f : -30000.f);
    };

    float o[2][8][4] = {};
    float ol[2][4] = {};                    // ones-column accumulators (l)

    load_tile(it0); CP_COMMIT();

    for (int it = it0; it < it1; it++) {
        CP_WAIT0();
        __syncthreads();
        if (it < it1 - 1) { load_tile(it + 1); CP_COMMIT(); }

        const int bsel = it & 1;
        const char* kbuf = smc + SM_BUF0 + bsel * BUF_BYTES;
        const char* vbuf = kbuf + KF_BYTES;
        const __half* mb = maskh + bsel * 64;

        // ---- S = mask_bias + Q @ K^T  (f16 accumulators) ----
        uint32_t s[2][8][2];
        #pragma unroll
        for (int ni = 0; ni < 8; ni++) {
            uint32_t m2 = *(const uint32_t*)(mb + ni * 8 + 2 * t);
            s[0][ni][0] = m2; s[0][ni][1] = m2;
            s[1][ni][0] = m2; s[1][ni][1] = m2;
        }
        #pragma unroll
        for (int kb = 0; kb < 4; kb++) {
            const char* kp = kbuf + kb * KB_STRIDE + (q + kb) * 32 + t * 8;
            #pragma unroll
            for (int ni = 0; ni < 8; ni++) {
                uint2 b = *(const uint2*)(kp + ni * 256);
                mma16h(s[0][ni][0], s[0][ni][1],
                       qa[0][kb][0], qa[0][kb][1], qa[0][kb][2], qa[0][kb][3], b.x, b.y);
                mma16h(s[1][ni][0], s[1][ni][1],
                       qa[1][kb][0], qa[1][kb][1], qa[1][kb][2], qa[1][kb][3], b.x, b.y);
            }
        }

        // ---- softmax: p = ex2(s) in place; s IS the PV A-fragment set ----
        #pragma unroll
        for (int ni = 0; ni < 8; ni++) {
            s[0][ni][0] = ex2h2(s[0][ni][0]); s[0][ni][1] = ex2h2(s[0][ni][1]);
            s[1][ni][0] = ex2h2(s[1][ni][0]); s[1][ni][1] = ex2h2(s[1][ni][1]);
        }

        // ---- O += P @ V, plus ones-column for l ----
        #pragma unroll
        for (int jb = 0; jb < 4; jb++) {
            const char* vp = vbuf + jb * KB_STRIDE + (q + jb) * 32 + t * 8;
            #pragma unroll
            for (int ni = 0; ni < 8; ni++) {
                uint2 b = *(const uint2*)(vp + ni * 256);
                mma16(o[0][ni], s[0][2*jb][0], s[0][2*jb][1],
                                s[0][2*jb+1][0], s[0][2*jb+1][1], b.x, b.y);
                mma16(o[1][ni], s[1][2*jb][0], s[1][2*jb][1],
                                s[1][2*jb+1][0], s[1][2*jb+1][1], b.x, b.y);
            }
            mma16(ol[0], s[0][2*jb][0], s[0][2*jb][1],
                         s[0][2*jb+1][0], s[0][2*jb+1][1], ONES_H2, ONES_H2);
            mma16(ol[1], s[1][2*jb][0], s[1][2*jb][1],
                         s[1][2*jb+1][0], s[1][2*jb+1][1], ONES_H2, ONES_H2);
        }
    }

    // ---- write UNNORMALIZED partials (interleaved columns) + l ----
    #pragma unroll
    for (int blk = 0; blk < 2; blk++) {
        const int rr = q0 + r0 + blk * 16;
        #pragma unroll
        for (int ni = 0; ni < 8; ni++) {
            int col = (ni >> 1) * 16 + 4 * t + 2 * (ni & 1);   // interleaved
            *(float2*)&gOp[base + (size_t)(rr    ) * DK_ + col] =
                make_float2(o[blk][ni][0], o[blk][ni][1]);
            *(float2*)&gOp[base + (size_t)(rr + 8) * DK_ + col] =
                make_float2(o[blk][ni][2], o[blk][ni][3]);
        }
        gLp[(size_t)bh * S_ + rr    ] = ol[blk][0];   // quad lanes dup-write same value
        gLp[(size_t)bh * S_ + rr + 8] = ol[blk][2];
    }
}

// ---------------- combine: GOH = (OP0 + OP1) / (l0 + l1), f16 ----------------
__global__ __launch_bounds__(256) void combine_kernel()
{
    const float* p0 = (const float*)(g_scr + OFF_OP0);
    const float* p1 = (const float*)(g_scr + OFF_OP1);
    const float* lp = (const float*)(g_scr + OFF_LP);
    __half* out = (__half*)(g_scr + OFF_GOH);

    size_t i = (size_t)(blockIdx.x * 256 + threadIdx.x) * 8;   // 8 floats
    int row = (int)(i >> 6);
    float l = lp[row] + lp[B_ * H_ * S_ + row];
    float inv = (l > 0.f) ? (1.f / l) : 0.f;
    float4 a0 = *(const float4*)&p0[i],     a1 = *(const float4*)&p0[i + 4];
    float4 b0 = *(const float4*)&p1[i],     b1 = *(const float4*)&p1[i + 4];
    uint4 r;
    r.x = packh2((a0.x + b0.x) * inv, (a0.y + b0.y) * inv);
    r.y = packh2((a0.z + b0.z) * inv, (a0.w + b0.w) * inv);
    r.z = packh2((a1.x + b1.x) * inv, (a1.y + b1.y) * inv);
    r.w = packh2((a1.z + b1.z) * inv, (a1.w + b1.w) * inv);
    *(uint4*)&out[i] = r;
}

// ---------------- launch ----------------
extern "C" void kernel_launch(void* const* d_in, const int* in_sizes, int n_in,
                              void* d_out, int out_size)
{
    const float* q    = (const float*)d_in[0];
    const float* k    = (const float*)d_in[1];
    const float* v    = (const float*)d_in[2];
    const int*   mask = (const int*)  d_in[3];
    const float* Wq   = (const float*)d_in[4];
    const float* Wk   = (const float*)d_in[5];
    const float* Wv   = (const float*)d_in[6];
    const float* Wo   = (const float*)d_in[7];
    float* out = (float*)d_out;

    cudaFuncSetAttribute(attn_kernel,
                         cudaFuncAttributeMaxDynamicSharedMemorySize, ATT_SMEM);
    cudaFuncSetAttribute(proj_qkv,
                         cudaFuncAttributeMaxDynamicSharedMemorySize, PJ_SMEM);
    cudaFuncSetAttribute(proj_out,
                         cudaFuncAttributeMaxDynamicSharedMemorySize, PJ_SMEM);

    // fold 1/sqrt(DK) * log2(e) into Q so attention works in exp2 domain
    const float qscale = 0.125f * 1.4426950408889634f;

    cvt_f16<<<dim3((M_ * D_) / (256 * 16), 1, 7), 256>>>(q, k, v, Wq, Wk, Wv, Wo);
    proj_qkv<<<dim3(D_ / 128, M_ / 128, 3), 256, PJ_SMEM>>>(qscale);
    attn_kernel<<<dim3(S_ / 128, B_ * H_, 2), 128, ATT_SMEM>>>(mask);
    combine_kernel<<<(M_ * D_) / (256 * 8), 256>>>();
    proj_out<<<dim3(D_ / 128, M_ / 128), 256, PJ_SMEM>>>(out);
}